// round 13
// baseline (speedup 1.0000x reference)
#include <cuda_runtime.h>
#include <cuda_fp16.h>
#include <math.h>
#include <stdint.h>

#define NTOK 2048

// ---------------- scratch (fp16 operands) ----------------
__device__ __half g_xh [(size_t)4096 * 1024];       // x       [m][k]
__device__ __half g_wqt[(size_t)1024 * 1024];       // Wq^T    [n][k]
__device__ __half g_wkt[(size_t)256  * 1024];
__device__ __half g_wvt[(size_t)256  * 1024];
__device__ __half g_wot[(size_t)1024 * 1024];
__device__ __half g_q [(size_t)2 * 16 * NTOK * 64]; // [b][h][n][d], q*(log2e/8)
__device__ __half g_k [(size_t)2 * 4  * NTOK * 64];
__device__ __half g_vt[(size_t)2 * 4  * 64 * NTOK]; // [b][kv][d][n]
__device__ __half g_o [(size_t)4096 * 1024];

__device__ __forceinline__ uint32_t PK2(float a, float b) {
    __half2 h = __floats2half2_rn(a, b);
    return *(uint32_t*)&h;
}
__device__ __forceinline__ uint32_t EX2H2(uint32_t x) {
    uint32_t y; asm("ex2.approx.f16x2 %0, %1;" : "=r"(y) : "r"(x));
    return y;
}
__device__ __forceinline__ uint32_t smem_u32(const void* p) {
    uint32_t a;
    asm("{ .reg .u64 t; cvta.to.shared.u64 t, %1; cvt.u32.u64 %0, t; }"
        : "=r"(a) : "l"(p));
    return a;
}

// D(16x8,f32) += A(16x16,f16) * B(16x8,f16)
__device__ __forceinline__ void mma16(float* d, uint32_t a0, uint32_t a1,
                                      uint32_t a2, uint32_t a3,
                                      uint32_t b0, uint32_t b1) {
    asm volatile(
        "mma.sync.aligned.m16n8k16.row.col.f32.f16.f16.f32 "
        "{%0,%1,%2,%3},{%4,%5,%6,%7},{%8,%9},{%0,%1,%2,%3};\n"
        : "+f"(d[0]), "+f"(d[1]), "+f"(d[2]), "+f"(d[3])
        : "r"(a0), "r"(a1), "r"(a2), "r"(a3), "r"(b0), "r"(b1));
}

#define LDSM4(r0, r1, r2, r3, addr) \
    asm volatile("ldmatrix.sync.aligned.m8n8.x4.shared.b16 {%0,%1,%2,%3}, [%4];" \
                 : "=r"(r0), "=r"(r1), "=r"(r2), "=r"(r3) : "r"(addr))

#define CP_ASYNC16(dst, src) \
    asm volatile("cp.async.cg.shared.global [%0], [%1], 16;\n" :: "r"(dst), "l"(src))
#define CP_COMMIT() asm volatile("cp.async.commit_group;\n" ::: "memory")
#define CP_WAIT0()  asm volatile("cp.async.wait_group 0;\n" ::: "memory")
#define CP_WAIT1()  asm volatile("cp.async.wait_group 1;\n" ::: "memory")

// =============================================================================
// Prep A: x -> fp16
// =============================================================================
__global__ __launch_bounds__(256) void cvtx_kernel(const float4* __restrict__ x)
{
    int i = blockIdx.x * 256 + threadIdx.x;   // 1048576 float4
    float4 v = x[i];
    uint2 o;
    o.x = PK2(v.x, v.y);
    o.y = PK2(v.z, v.w);
    ((uint2*)g_xh)[i] = o;
}

// =============================================================================
// Prep B: weights -> fp16 + transpose to [n][k]
// =============================================================================
__global__ __launch_bounds__(256) void wtr_kernel(
    const float* __restrict__ wq, const float* __restrict__ wk,
    const float* __restrict__ wv, const float* __restrict__ wo)
{
    __shared__ float ts[32][33];
    int t = blockIdx.x;
    const float* src; __half* dst; int N;
    if (t < 1024)      { src = wq; dst = g_wqt; N = 1024; }
    else if (t < 1280) { src = wk; dst = g_wkt; N = 256;  t -= 1024; }
    else if (t < 1536) { src = wv; dst = g_wvt; N = 256;  t -= 1280; }
    else               { src = wo; dst = g_wot; N = 1024; t -= 1536; }
    int tiles_n = N >> 5;
    int k0 = (t / tiles_n) << 5, n0 = (t % tiles_n) << 5;
    int tx = threadIdx.x & 31, ty = threadIdx.x >> 5;
    #pragma unroll
    for (int p = 0; p < 4; p++)
        ts[ty + p * 8][tx] = src[(size_t)(k0 + ty + p * 8) * N + n0 + tx];
    __syncthreads();
    #pragma unroll
    for (int p = 0; p < 4; p++)
        dst[(size_t)(n0 + ty + p * 8) * 1024 + k0 + tx] = __float2half(ts[tx][ty + p * 8]);
}

// =============================================================================
// fp16 GEMM mainloop: 128 thr / 4 warps, tile 128x64, k-step 32, 2-stage.
// =============================================================================
#define APAD 40
#define A_SZ (128 * APAD)
#define B_SZ (64 * APAD)

__device__ __forceinline__ void gemm_fp16(
    const __half* __restrict__ A, const __half* __restrict__ Bt,
    __half* sa, __half* sb, int tid, int w, int lane, float acc[2][8][4])
{
    const uint32_t as_u = smem_u32(sa);
    const uint32_t bs_u = smem_u32(sb);
    const int ldr = tid >> 2, ldc = tid & 3;

    const int m_ = lane >> 3, r_ = lane & 7;
    const uint32_t a_off = ((m_ & 1) * 8 + r_) * (APAD * 2) + (m_ >> 1) * 16;
    const uint32_t b_off = ((m_ >> 1) * 8 + r_) * (APAD * 2) + (m_ & 1) * 16;

    #pragma unroll
    for (int p = 0; p < 4; p++)
        CP_ASYNC16(as_u + ((p * 32 + ldr) * APAD) * 2 + ldc * 16,
                   &A[(size_t)(p * 32 + ldr) * 1024 + ldc * 8]);
    #pragma unroll
    for (int p = 0; p < 2; p++)
        CP_ASYNC16(bs_u + ((p * 32 + ldr) * APAD) * 2 + ldc * 16,
                   &Bt[(size_t)(p * 32 + ldr) * 1024 + ldc * 8]);
    CP_COMMIT();

    for (int i = 0; i < 32; i++) {
        const int cur = i & 1;
        if (i + 1 < 32) {
            const int nxt = 1 - cur;
            const int k0 = (i + 1) * 32;
            #pragma unroll
            for (int p = 0; p < 4; p++)
                CP_ASYNC16(as_u + (nxt * A_SZ + (p * 32 + ldr) * APAD) * 2 + ldc * 16,
                           &A[(size_t)(p * 32 + ldr) * 1024 + k0 + ldc * 8]);
            #pragma unroll
            for (int p = 0; p < 2; p++)
                CP_ASYNC16(bs_u + (nxt * B_SZ + (p * 32 + ldr) * APAD) * 2 + ldc * 16,
                           &Bt[(size_t)(p * 32 + ldr) * 1024 + k0 + ldc * 8]);
            CP_COMMIT();
            CP_WAIT1();
        } else {
            CP_WAIT0();
        }
        __syncthreads();

        const uint32_t ab = as_u + cur * A_SZ * 2;
        const uint32_t bb = bs_u + cur * B_SZ * 2;
        #pragma unroll
        for (int ks = 0; ks < 2; ks++) {
            uint32_t af[2][4];
            #pragma unroll
            for (int mt = 0; mt < 2; mt++)
                LDSM4(af[mt][0], af[mt][1], af[mt][2], af[mt][3],
                      ab + (w * 32 + mt * 16) * (APAD * 2) + ks * 32 + a_off);
            #pragma unroll
            for (int p = 0; p < 4; p++) {
                uint32_t b0a, b1a, b0b, b1b;
                LDSM4(b0a, b1a, b0b, b1b,
                      bb + (p * 16) * (APAD * 2) + ks * 32 + b_off);
                #pragma unroll
                for (int mt = 0; mt < 2; mt++) {
                    mma16(acc[mt][2 * p],     af[mt][0], af[mt][1], af[mt][2], af[mt][3], b0a, b1a);
                    mma16(acc[mt][2 * p + 1], af[mt][0], af[mt][1], af[mt][2], af[mt][3], b0b, b1b);
                }
            }
        }
        __syncthreads();
    }
}

// =============================================================================
// Kernel 1: QKV GEMM + bias + RMSNorm + 3D RoPE + q-scale (0.125*log2e)
// =============================================================================
__global__ __launch_bounds__(128) void qkv_kernel(
    const float* __restrict__ bq, const float* __restrict__ bk,
    const float* __restrict__ bv,
    const float* __restrict__ qn, const float* __restrict__ kn)
{
    __shared__ __half sa[2 * A_SZ];
    __shared__ __half sb[2 * B_SZ];
    const int tid = threadIdx.x;
    const int w = tid >> 5, lane = tid & 31, g = lane >> 2, c = lane & 3;
    const int m0 = blockIdx.y * 128;
    const int colb = blockIdx.x * 64;

    const __half* Bt; const float* bias; int seg, colloc;
    if (colb < 1024)      { Bt = g_wqt; bias = bq; seg = 0; colloc = colb; }
    else if (colb < 1280) { Bt = g_wkt; bias = bk; seg = 1; colloc = colb - 1024; }
    else                  { Bt = g_wvt; bias = bv; seg = 2; colloc = colb - 1280; }

    float acc[2][8][4] = {};
    gemm_fp16(g_xh + (size_t)m0 * 1024, Bt + (size_t)colloc * 1024,
              sa, sb, tid, w, lane, acc);

    #pragma unroll
    for (int nt = 0; nt < 8; nt++) {
        float b0v = bias[colloc + nt * 8 + 2 * c];
        float b1v = bias[colloc + nt * 8 + 2 * c + 1];
        #pragma unroll
        for (int mt = 0; mt < 2; mt++) {
            acc[mt][nt][0] += b0v; acc[mt][nt][1] += b1v;
            acc[mt][nt][2] += b0v; acc[mt][nt][3] += b1v;
        }
    }

    const int head = colloc >> 6;

    if (seg == 2) {
        #pragma unroll
        for (int mt = 0; mt < 2; mt++) {
            int m_a = m0 + w * 32 + mt * 16 + g;
            int b_ = m_a >> 11, n0 = m_a & 2047, n1 = n0 + 8;
            __half* vb = &g_vt[((size_t)(b_ * 4 + head)) * 64 * NTOK];
            #pragma unroll
            for (int nt = 0; nt < 8; nt++) {
                int d0 = nt * 8 + 2 * c;
                vb[(size_t)d0 * NTOK + n0]       = __float2half(acc[mt][nt][0]);
                vb[(size_t)(d0 + 1) * NTOK + n0] = __float2half(acc[mt][nt][1]);
                vb[(size_t)d0 * NTOK + n1]       = __float2half(acc[mt][nt][2]);
                vb[(size_t)(d0 + 1) * NTOK + n1] = __float2half(acc[mt][nt][3]);
            }
        }
        return;
    }

    // RMSNorm (intra-warp over 64-wide head dim)
    const float* nw = (seg == 0) ? qn : kn;
    #pragma unroll
    for (int mt = 0; mt < 2; mt++) {
        float ss0 = 0.f, ss1 = 0.f;
        #pragma unroll
        for (int nt = 0; nt < 8; nt++) {
            ss0 += acc[mt][nt][0] * acc[mt][nt][0] + acc[mt][nt][1] * acc[mt][nt][1];
            ss1 += acc[mt][nt][2] * acc[mt][nt][2] + acc[mt][nt][3] * acc[mt][nt][3];
        }
        ss0 += __shfl_xor_sync(~0u, ss0, 1); ss0 += __shfl_xor_sync(~0u, ss0, 2);
        ss1 += __shfl_xor_sync(~0u, ss1, 1); ss1 += __shfl_xor_sync(~0u, ss1, 2);
        float rs0 = rsqrtf(ss0 * (1.f / 64.f) + 1e-6f);
        float rs1 = rsqrtf(ss1 * (1.f / 64.f) + 1e-6f);
        #pragma unroll
        for (int nt = 0; nt < 8; nt++) {
            float w0 = nw[nt * 8 + 2 * c], w1 = nw[nt * 8 + 2 * c + 1];
            acc[mt][nt][0] *= rs0 * w0; acc[mt][nt][1] *= rs0 * w1;
            acc[mt][nt][2] *= rs1 * w0; acc[mt][nt][3] *= rs1 * w1;
        }
    }

    // 3D RoPE in-place: pairs t:(0,1) h:(2,3) w:(4,6),(5,7)
    const int lo_[4] = {0, 2, 4, 5};
    const int hi_[4] = {1, 3, 6, 7};
    #pragma unroll
    for (int mt = 0; mt < 2; mt++) {
        int m_a = m0 + w * 32 + mt * 16 + g;
        int n0 = m_a & 2047, n1 = n0 + 8;
        float posr[2][3] = {
            {(float)(n0 >> 8), (float)((n0 >> 4) & 15), (float)(n0 & 15)},
            {(float)(n1 >> 8), (float)((n1 >> 4) & 15), (float)(n1 & 15)}};
        #pragma unroll
        for (int pi = 0; pi < 4; pi++) {
            int lo = lo_[pi], hi = hi_[pi];
            int ax = (pi == 0) ? 0 : (pi == 1 ? 1 : 2);
            float halfinv = (pi < 2) ? (1.f / 8.f) : (1.f / 16.f);
            #pragma unroll
            for (int e = 0; e < 2; e++) {
                float f = (pi < 2) ? (float)(2 * c + e)
                                   : (float)((lo & 1) * 8 + 2 * c + e);
                float inv = __powf(10000.f, -f * halfinv);
                #pragma unroll
                for (int r = 0; r < 2; r++) {
                    float sv, cv;
                    __sincosf(posr[r][ax] * inv, &sv, &cv);
                    float xl = acc[mt][lo][2 * r + e];
                    float xh = acc[mt][hi][2 * r + e];
                    acc[mt][lo][2 * r + e] = xl * cv - xh * sv;
                    acc[mt][hi][2 * r + e] = xh * cv + xl * sv;
                }
            }
        }
    }

    float sc = (seg == 0) ? (0.125f * 1.4426950408889634f) : 1.f;
    #pragma unroll
    for (int mt = 0; mt < 2; mt++) {
        int m_a = m0 + w * 32 + mt * 16 + g;
        int b_ = m_a >> 11, n0 = m_a & 2047, n1 = n0 + 8;
        __half* qb = (seg == 0) ? &g_q[((size_t)(b_ * 16 + head)) * NTOK * 64]
                                : &g_k[((size_t)(b_ * 4 + head)) * NTOK * 64];
        #pragma unroll
        for (int nt = 0; nt < 8; nt++) {
            int d0 = nt * 8 + 2 * c;
            *(uint32_t*)&qb[(size_t)n0 * 64 + d0] = PK2(acc[mt][nt][0] * sc, acc[mt][nt][1] * sc);
            *(uint32_t*)&qb[(size_t)n1 * 64 + d0] = PK2(acc[mt][nt][2] * sc, acc[mt][nt][3] * sc);
        }
    }
}

// =============================================================================
// Kernel 2: flash attention fp16. q-block 64, 4 warps, warp M=16.
//   ~105 regs -> 4 CTAs/SM (592 slots) vs grid 1024: wave util 86% (was 58%).
//   ex2.f16x2 softmax; rowsum via ones-mma; K+V double-buffered cp.async.
// =============================================================================
#define KVP 72
#define H2_ONES 0x3C003C00u

__global__ __launch_bounds__(128, 4) void attn_kernel()
{
    __shared__ __half kvs[2][2][64 * KVP];   // [buf][K/V][...]

    const int tid = threadIdx.x;
    const int w = tid >> 5, lane = tid & 31, g = lane >> 2, c = lane & 3;
    const int q0 = blockIdx.x * 64;
    const int bh = blockIdx.y;
    const int b_ = bh >> 4, h = bh & 15, kv = h >> 2;

    const __half* qg = &g_q[((size_t)(b_ * 16 + h)) * NTOK * 64];
    const __half* kg = &g_k[((size_t)(b_ * 4 + kv)) * NTOK * 64];
    const __half* vg = &g_vt[((size_t)(b_ * 4 + kv)) * 64 * NTOK];

    const int lr = tid >> 1, lc = tid & 1;
    const uint32_t k_u = smem_u32(&kvs[0][0][0]) + lr * (KVP * 2) + lc * 64;
    const uint32_t v_u = smem_u32(&kvs[0][1][0]) + lr * (KVP * 2) + lc * 64;
    const uint32_t bufstride = 2 * 64 * KVP * 2;

    const int m_ = lane >> 3, r_ = lane & 7;
    const uint32_t b_off = ((m_ >> 1) * 8 + r_) * (KVP * 2) + (m_ & 1) * 16;
    const uint32_t kbase = smem_u32(&kvs[0][0][0]) + b_off;
    const uint32_t vbase = smem_u32(&kvs[0][1][0]) + b_off;

    // Q fragments register-resident (warp rows q0+w*16+g, +8)
    uint32_t qf[4][4];
    {
        const __half* r0 = &qg[(size_t)(q0 + w * 16 + g) * 64];
        #pragma unroll
        for (int kc = 0; kc < 4; kc++) {
            qf[kc][0] = *(const uint32_t*)&r0[kc * 16 + 2 * c];
            qf[kc][1] = *(const uint32_t*)&r0[8 * 64 + kc * 16 + 2 * c];
            qf[kc][2] = *(const uint32_t*)&r0[kc * 16 + 8 + 2 * c];
            qf[kc][3] = *(const uint32_t*)&r0[8 * 64 + kc * 16 + 8 + 2 * c];
        }
    }

    float o[8][4] = {};
    float lpa[4] = {};

    // prologue: K0 + V0
    #pragma unroll
    for (int i = 0; i < 4; i++) {
        CP_ASYNC16(k_u + i * 16, &kg[(size_t)lr * 64 + lc * 32 + i * 8]);
        CP_ASYNC16(v_u + i * 16, &vg[(size_t)lr * NTOK + lc * 32 + i * 8]);
    }
    CP_COMMIT();

    for (int kt = 0; kt < NTOK; kt += 64) {
        const int buf = (kt >> 6) & 1;
        CP_WAIT0();
        __syncthreads();

        if (kt + 64 < NTOK) {
            const uint32_t off = (1 - buf) * bufstride;
            #pragma unroll
            for (int i = 0; i < 4; i++) {
                CP_ASYNC16(k_u + off + i * 16, &kg[(size_t)(kt + 64 + lr) * 64 + lc * 32 + i * 8]);
                CP_ASYNC16(v_u + off + i * 16, &vg[(size_t)lr * NTOK + kt + 64 + lc * 32 + i * 8]);
            }
            CP_COMMIT();
        }

        const uint32_t kb = kbase + buf * bufstride;
        const uint32_t vb = vbase + buf * bufstride;

        // S = Q K^T  (16 q-rows x 64 keys)
        float s[8][4] = {};
        #pragma unroll
        for (int kc = 0; kc < 4; kc++) {
            #pragma unroll
            for (int p = 0; p < 4; p++) {
                uint32_t b0a, b1a, b0b, b1b;
                LDSM4(b0a, b1a, b0b, b1b, kb + p * 16 * (KVP * 2) + kc * 32);
                mma16(s[2 * p],     qf[kc][0], qf[kc][1], qf[kc][2], qf[kc][3], b0a, b1a);
                mma16(s[2 * p + 1], qf[kc][0], qf[kc][1], qf[kc][2], qf[kc][3], b0b, b1b);
            }
        }

        // P = 2^S (fp16-packed) ; rowsum via ones-mma
        uint32_t pa[4][4];
        #pragma unroll
        for (int kc = 0; kc < 4; kc++) {
            pa[kc][0] = EX2H2(PK2(s[2 * kc][0],     s[2 * kc][1]));
            pa[kc][1] = EX2H2(PK2(s[2 * kc][2],     s[2 * kc][3]));
            pa[kc][2] = EX2H2(PK2(s[2 * kc + 1][0], s[2 * kc + 1][1]));
            pa[kc][3] = EX2H2(PK2(s[2 * kc + 1][2], s[2 * kc + 1][3]));
        }
        #pragma unroll
        for (int kc = 0; kc < 4; kc++)
            mma16(lpa, pa[kc][0], pa[kc][1], pa[kc][2], pa[kc][3], H2_ONES, H2_ONES);

        // O += P V
        #pragma unroll
        for (int kc = 0; kc < 4; kc++) {
            #pragma unroll
            for (int p = 0; p < 4; p++) {
                uint32_t b0a, b1a, b0b, b1b;
                LDSM4(b0a, b1a, b0b, b1b, vb + p * 16 * (KVP * 2) + kc * 32);
                mma16(o[2 * p],     pa[kc][0], pa[kc][1], pa[kc][2], pa[kc][3], b0a, b1a);
                mma16(o[2 * p + 1], pa[kc][0], pa[kc][1], pa[kc][2], pa[kc][3], b0b, b1b);
            }
        }
    }

    float inv0 = 1.f / lpa[0], inv1 = 1.f / lpa[2];
    int n0 = q0 + w * 16 + g, n1 = n0 + 8;
    __half* ob0 = &g_o[((size_t)(b_ * NTOK + n0)) * 1024 + h * 64];
    __half* ob1 = &g_o[((size_t)(b_ * NTOK + n1)) * 1024 + h * 64];
    #pragma unroll
    for (int nt = 0; nt < 8; nt++) {
        int d0 = nt * 8 + 2 * c;
        *(uint32_t*)&ob0[d0] = PK2(o[nt][0] * inv0, o[nt][1] * inv0);
        *(uint32_t*)&ob1[d0] = PK2(o[nt][2] * inv1, o[nt][3] * inv1);
    }
}

// =============================================================================
// Kernel 3: out = O @ Wo + bo  (fp16 operands, fp32 out)
// =============================================================================
__global__ __launch_bounds__(128) void out_kernel(
    const float* __restrict__ bo, float* __restrict__ out)
{
    __shared__ __half sa[2 * A_SZ];
    __shared__ __half sb[2 * B_SZ];
    const int tid = threadIdx.x;
    const int w = tid >> 5, lane = tid & 31, g = lane >> 2, c = lane & 3;
    const int m0 = blockIdx.y * 128;
    const int colb = blockIdx.x * 64;

    float acc[2][8][4] = {};
    gemm_fp16(g_o + (size_t)m0 * 1024, g_wot + (size_t)colb * 1024,
              sa, sb, tid, w, lane, acc);

    #pragma unroll
    for (int mt = 0; mt < 2; mt++) {
        int m_a = m0 + w * 32 + mt * 16 + g;
        float* r0 = &out[(size_t)m_a * 1024 + colb];
        float* r1 = &out[(size_t)(m_a + 8) * 1024 + colb];
        #pragma unroll
        for (int nt = 0; nt < 8; nt++) {
            int d0 = nt * 8 + 2 * c;
            float b0v = bo[colb + d0], b1v = bo[colb + d0 + 1];
            *(float2*)&r0[d0] = make_float2(acc[mt][nt][0] + b0v, acc[mt][nt][1] + b1v);
            *(float2*)&r1[d0] = make_float2(acc[mt][nt][2] + b0v, acc[mt][nt][3] + b1v);
        }
    }
}

// =============================================================================
extern "C" void kernel_launch(void* const* d_in, const int* in_sizes, int n_in,
                              void* d_out, int out_size)
{
    const float* x  = (const float*)d_in[0];
    const float* Wq = (const float*)d_in[1];
    const float* bq = (const float*)d_in[2];
    const float* Wk = (const float*)d_in[3];
    const float* bk = (const float*)d_in[4];
    const float* Wv = (const float*)d_in[5];
    const float* bv = (const float*)d_in[6];
    const float* Wo = (const float*)d_in[7];
    const float* bo = (const float*)d_in[8];
    const float* qn = (const float*)d_in[9];
    const float* kn = (const float*)d_in[10];
    float* out = (float*)d_out;

    cvtx_kernel<<<4096, 256>>>((const float4*)x);
    wtr_kernel<<<2560, 256>>>(Wq, Wk, Wv, Wo);
    qkv_kernel<<<dim3(24, 32), 128>>>(bq, bk, bv, qn, kn);
    attn_kernel<<<dim3(32, 32), 128>>>();
    out_kernel<<<dim3(16, 32), 128>>>(bo, out);
}

// round 14
// speedup vs baseline: 1.0272x; 1.0272x over previous
#include <cuda_runtime.h>
#include <cuda_fp16.h>
#include <math.h>
#include <stdint.h>

#define NTOK 2048

// ---------------- scratch (fp16 operands) ----------------
__device__ __half g_xh [(size_t)4096 * 1024];       // x       [m][k]
__device__ __half g_wqt[(size_t)1024 * 1024];       // Wq^T    [n][k]
__device__ __half g_wkt[(size_t)256  * 1024];
__device__ __half g_wvt[(size_t)256  * 1024];
__device__ __half g_wot[(size_t)1024 * 1024];
__device__ __half g_q [(size_t)2 * 16 * NTOK * 64]; // [b][h][n][d], q*(log2e/8)
__device__ __half g_k [(size_t)2 * 4  * NTOK * 64];
__device__ __half g_vt[(size_t)2 * 4  * 64 * NTOK]; // [b][kv][d][n]
__device__ __half g_o [(size_t)4096 * 1024];

__device__ __forceinline__ uint32_t PK2(float a, float b) {
    __half2 h = __floats2half2_rn(a, b);
    return *(uint32_t*)&h;
}
__device__ __forceinline__ uint32_t EX2H2(uint32_t x) {
    uint32_t y; asm("ex2.approx.f16x2 %0, %1;" : "=r"(y) : "r"(x));
    return y;
}
__device__ __forceinline__ uint32_t smem_u32(const void* p) {
    uint32_t a;
    asm("{ .reg .u64 t; cvta.to.shared.u64 t, %1; cvt.u32.u64 %0, t; }"
        : "=r"(a) : "l"(p));
    return a;
}

// D(16x8,f32) += A(16x16,f16) * B(16x8,f16)
__device__ __forceinline__ void mma16(float* d, uint32_t a0, uint32_t a1,
                                      uint32_t a2, uint32_t a3,
                                      uint32_t b0, uint32_t b1) {
    asm volatile(
        "mma.sync.aligned.m16n8k16.row.col.f32.f16.f16.f32 "
        "{%0,%1,%2,%3},{%4,%5,%6,%7},{%8,%9},{%0,%1,%2,%3};\n"
        : "+f"(d[0]), "+f"(d[1]), "+f"(d[2]), "+f"(d[3])
        : "r"(a0), "r"(a1), "r"(a2), "r"(a3), "r"(b0), "r"(b1));
}

#define LDSM4(r0, r1, r2, r3, addr) \
    asm volatile("ldmatrix.sync.aligned.m8n8.x4.shared.b16 {%0,%1,%2,%3}, [%4];" \
                 : "=r"(r0), "=r"(r1), "=r"(r2), "=r"(r3) : "r"(addr))

#define CP_ASYNC16(dst, src) \
    asm volatile("cp.async.cg.shared.global [%0], [%1], 16;\n" :: "r"(dst), "l"(src))
#define CP_COMMIT() asm volatile("cp.async.commit_group;\n" ::: "memory")
#define CP_WAIT0()  asm volatile("cp.async.wait_group 0;\n" ::: "memory")
#define CP_WAIT1()  asm volatile("cp.async.wait_group 1;\n" ::: "memory")

// =============================================================================
// Prep A: x -> fp16
// =============================================================================
__global__ __launch_bounds__(256) void cvtx_kernel(const float4* __restrict__ x)
{
    int i = blockIdx.x * 256 + threadIdx.x;   // 1048576 float4
    float4 v = x[i];
    uint2 o;
    o.x = PK2(v.x, v.y);
    o.y = PK2(v.z, v.w);
    ((uint2*)g_xh)[i] = o;
}

// =============================================================================
// Prep B: weights -> fp16 + transpose to [n][k]
// =============================================================================
__global__ __launch_bounds__(256) void wtr_kernel(
    const float* __restrict__ wq, const float* __restrict__ wk,
    const float* __restrict__ wv, const float* __restrict__ wo)
{
    __shared__ float ts[32][33];
    int t = blockIdx.x;
    const float* src; __half* dst; int N;
    if (t < 1024)      { src = wq; dst = g_wqt; N = 1024; }
    else if (t < 1280) { src = wk; dst = g_wkt; N = 256;  t -= 1024; }
    else if (t < 1536) { src = wv; dst = g_wvt; N = 256;  t -= 1280; }
    else               { src = wo; dst = g_wot; N = 1024; t -= 1536; }
    int tiles_n = N >> 5;
    int k0 = (t / tiles_n) << 5, n0 = (t % tiles_n) << 5;
    int tx = threadIdx.x & 31, ty = threadIdx.x >> 5;
    #pragma unroll
    for (int p = 0; p < 4; p++)
        ts[ty + p * 8][tx] = src[(size_t)(k0 + ty + p * 8) * N + n0 + tx];
    __syncthreads();
    #pragma unroll
    for (int p = 0; p < 4; p++)
        dst[(size_t)(n0 + ty + p * 8) * 1024 + k0 + tx] = __float2half(ts[tx][ty + p * 8]);
}

// =============================================================================
// fp16 GEMM mainloop: 128 thr / 4 warps, tile 128x64, k-step 32, 2-stage.
// =============================================================================
#define APAD 40
#define A_SZ (128 * APAD)
#define B_SZ (64 * APAD)

__device__ __forceinline__ void gemm_fp16(
    const __half* __restrict__ A, const __half* __restrict__ Bt,
    __half* sa, __half* sb, int tid, int w, int lane, float acc[2][8][4])
{
    const uint32_t as_u = smem_u32(sa);
    const uint32_t bs_u = smem_u32(sb);
    const int ldr = tid >> 2, ldc = tid & 3;

    const int m_ = lane >> 3, r_ = lane & 7;
    const uint32_t a_off = ((m_ & 1) * 8 + r_) * (APAD * 2) + (m_ >> 1) * 16;
    const uint32_t b_off = ((m_ >> 1) * 8 + r_) * (APAD * 2) + (m_ & 1) * 16;

    #pragma unroll
    for (int p = 0; p < 4; p++)
        CP_ASYNC16(as_u + ((p * 32 + ldr) * APAD) * 2 + ldc * 16,
                   &A[(size_t)(p * 32 + ldr) * 1024 + ldc * 8]);
    #pragma unroll
    for (int p = 0; p < 2; p++)
        CP_ASYNC16(bs_u + ((p * 32 + ldr) * APAD) * 2 + ldc * 16,
                   &Bt[(size_t)(p * 32 + ldr) * 1024 + ldc * 8]);
    CP_COMMIT();

    for (int i = 0; i < 32; i++) {
        const int cur = i & 1;
        if (i + 1 < 32) {
            const int nxt = 1 - cur;
            const int k0 = (i + 1) * 32;
            #pragma unroll
            for (int p = 0; p < 4; p++)
                CP_ASYNC16(as_u + (nxt * A_SZ + (p * 32 + ldr) * APAD) * 2 + ldc * 16,
                           &A[(size_t)(p * 32 + ldr) * 1024 + k0 + ldc * 8]);
            #pragma unroll
            for (int p = 0; p < 2; p++)
                CP_ASYNC16(bs_u + (nxt * B_SZ + (p * 32 + ldr) * APAD) * 2 + ldc * 16,
                           &Bt[(size_t)(p * 32 + ldr) * 1024 + k0 + ldc * 8]);
            CP_COMMIT();
            CP_WAIT1();
        } else {
            CP_WAIT0();
        }
        __syncthreads();

        const uint32_t ab = as_u + cur * A_SZ * 2;
        const uint32_t bb = bs_u + cur * B_SZ * 2;
        #pragma unroll
        for (int ks = 0; ks < 2; ks++) {
            uint32_t af[2][4];
            #pragma unroll
            for (int mt = 0; mt < 2; mt++)
                LDSM4(af[mt][0], af[mt][1], af[mt][2], af[mt][3],
                      ab + (w * 32 + mt * 16) * (APAD * 2) + ks * 32 + a_off);
            #pragma unroll
            for (int p = 0; p < 4; p++) {
                uint32_t b0a, b1a, b0b, b1b;
                LDSM4(b0a, b1a, b0b, b1b,
                      bb + (p * 16) * (APAD * 2) + ks * 32 + b_off);
                #pragma unroll
                for (int mt = 0; mt < 2; mt++) {
                    mma16(acc[mt][2 * p],     af[mt][0], af[mt][1], af[mt][2], af[mt][3], b0a, b1a);
                    mma16(acc[mt][2 * p + 1], af[mt][0], af[mt][1], af[mt][2], af[mt][3], b0b, b1b);
                }
            }
        }
        __syncthreads();
    }
}

// =============================================================================
// Kernel 1: QKV GEMM + bias + RMSNorm + 3D RoPE + q-scale (0.125*log2e)
// =============================================================================
__global__ __launch_bounds__(128) void qkv_kernel(
    const float* __restrict__ bq, const float* __restrict__ bk,
    const float* __restrict__ bv,
    const float* __restrict__ qn, const float* __restrict__ kn)
{
    __shared__ __half sa[2 * A_SZ];
    __shared__ __half sb[2 * B_SZ];
    const int tid = threadIdx.x;
    const int w = tid >> 5, lane = tid & 31, g = lane >> 2, c = lane & 3;
    const int m0 = blockIdx.y * 128;
    const int colb = blockIdx.x * 64;

    const __half* Bt; const float* bias; int seg, colloc;
    if (colb < 1024)      { Bt = g_wqt; bias = bq; seg = 0; colloc = colb; }
    else if (colb < 1280) { Bt = g_wkt; bias = bk; seg = 1; colloc = colb - 1024; }
    else                  { Bt = g_wvt; bias = bv; seg = 2; colloc = colb - 1280; }

    float acc[2][8][4] = {};
    gemm_fp16(g_xh + (size_t)m0 * 1024, Bt + (size_t)colloc * 1024,
              sa, sb, tid, w, lane, acc);

    #pragma unroll
    for (int nt = 0; nt < 8; nt++) {
        float b0v = bias[colloc + nt * 8 + 2 * c];
        float b1v = bias[colloc + nt * 8 + 2 * c + 1];
        #pragma unroll
        for (int mt = 0; mt < 2; mt++) {
            acc[mt][nt][0] += b0v; acc[mt][nt][1] += b1v;
            acc[mt][nt][2] += b0v; acc[mt][nt][3] += b1v;
        }
    }

    const int head = colloc >> 6;

    if (seg == 2) {
        #pragma unroll
        for (int mt = 0; mt < 2; mt++) {
            int m_a = m0 + w * 32 + mt * 16 + g;
            int b_ = m_a >> 11, n0 = m_a & 2047, n1 = n0 + 8;
            __half* vb = &g_vt[((size_t)(b_ * 4 + head)) * 64 * NTOK];
            #pragma unroll
            for (int nt = 0; nt < 8; nt++) {
                int d0 = nt * 8 + 2 * c;
                vb[(size_t)d0 * NTOK + n0]       = __float2half(acc[mt][nt][0]);
                vb[(size_t)(d0 + 1) * NTOK + n0] = __float2half(acc[mt][nt][1]);
                vb[(size_t)d0 * NTOK + n1]       = __float2half(acc[mt][nt][2]);
                vb[(size_t)(d0 + 1) * NTOK + n1] = __float2half(acc[mt][nt][3]);
            }
        }
        return;
    }

    // RMSNorm (intra-warp over 64-wide head dim)
    const float* nw = (seg == 0) ? qn : kn;
    #pragma unroll
    for (int mt = 0; mt < 2; mt++) {
        float ss0 = 0.f, ss1 = 0.f;
        #pragma unroll
        for (int nt = 0; nt < 8; nt++) {
            ss0 += acc[mt][nt][0] * acc[mt][nt][0] + acc[mt][nt][1] * acc[mt][nt][1];
            ss1 += acc[mt][nt][2] * acc[mt][nt][2] + acc[mt][nt][3] * acc[mt][nt][3];
        }
        ss0 += __shfl_xor_sync(~0u, ss0, 1); ss0 += __shfl_xor_sync(~0u, ss0, 2);
        ss1 += __shfl_xor_sync(~0u, ss1, 1); ss1 += __shfl_xor_sync(~0u, ss1, 2);
        float rs0 = rsqrtf(ss0 * (1.f / 64.f) + 1e-6f);
        float rs1 = rsqrtf(ss1 * (1.f / 64.f) + 1e-6f);
        #pragma unroll
        for (int nt = 0; nt < 8; nt++) {
            float w0 = nw[nt * 8 + 2 * c], w1 = nw[nt * 8 + 2 * c + 1];
            acc[mt][nt][0] *= rs0 * w0; acc[mt][nt][1] *= rs0 * w1;
            acc[mt][nt][2] *= rs1 * w0; acc[mt][nt][3] *= rs1 * w1;
        }
    }

    // 3D RoPE in-place: pairs t:(0,1) h:(2,3) w:(4,6),(5,7)
    const int lo_[4] = {0, 2, 4, 5};
    const int hi_[4] = {1, 3, 6, 7};
    #pragma unroll
    for (int mt = 0; mt < 2; mt++) {
        int m_a = m0 + w * 32 + mt * 16 + g;
        int n0 = m_a & 2047, n1 = n0 + 8;
        float posr[2][3] = {
            {(float)(n0 >> 8), (float)((n0 >> 4) & 15), (float)(n0 & 15)},
            {(float)(n1 >> 8), (float)((n1 >> 4) & 15), (float)(n1 & 15)}};
        #pragma unroll
        for (int pi = 0; pi < 4; pi++) {
            int lo = lo_[pi], hi = hi_[pi];
            int ax = (pi == 0) ? 0 : (pi == 1 ? 1 : 2);
            float halfinv = (pi < 2) ? (1.f / 8.f) : (1.f / 16.f);
            #pragma unroll
            for (int e = 0; e < 2; e++) {
                float f = (pi < 2) ? (float)(2 * c + e)
                                   : (float)((lo & 1) * 8 + 2 * c + e);
                float inv = __powf(10000.f, -f * halfinv);
                #pragma unroll
                for (int r = 0; r < 2; r++) {
                    float sv, cv;
                    __sincosf(posr[r][ax] * inv, &sv, &cv);
                    float xl = acc[mt][lo][2 * r + e];
                    float xh = acc[mt][hi][2 * r + e];
                    acc[mt][lo][2 * r + e] = xl * cv - xh * sv;
                    acc[mt][hi][2 * r + e] = xh * cv + xl * sv;
                }
            }
        }
    }

    float sc = (seg == 0) ? (0.125f * 1.4426950408889634f) : 1.f;
    #pragma unroll
    for (int mt = 0; mt < 2; mt++) {
        int m_a = m0 + w * 32 + mt * 16 + g;
        int b_ = m_a >> 11, n0 = m_a & 2047, n1 = n0 + 8;
        __half* qb = (seg == 0) ? &g_q[((size_t)(b_ * 16 + head)) * NTOK * 64]
                                : &g_k[((size_t)(b_ * 4 + head)) * NTOK * 64];
        #pragma unroll
        for (int nt = 0; nt < 8; nt++) {
            int d0 = nt * 8 + 2 * c;
            *(uint32_t*)&qb[(size_t)n0 * 64 + d0] = PK2(acc[mt][nt][0] * sc, acc[mt][nt][1] * sc);
            *(uint32_t*)&qb[(size_t)n1 * 64 + d0] = PK2(acc[mt][nt][2] * sc, acc[mt][nt][3] * sc);
        }
    }
}

// =============================================================================
// Kernel 2: flash attention fp16. q-block 128, 4 warps, warp M=32.
//   Per-16-key-chunk interleave (S-partial -> ex2 -> PV) cuts live regs to
//   ~115; Q staged in smem (loaded once). 4 CTAs/SM -> grid 512 in ONE wave.
// =============================================================================
#define KVP 72
#define Q_SZ (128 * KVP)            // halfs
#define KV_T (64 * KVP)             // halfs per K or V tile
#define ATTN_SMEM ((Q_SZ + 4 * KV_T) * 2)   // bytes: Q + 2 bufs x (K+V) = 55296
#define H2_ONES 0x3C003C00u

__global__ __launch_bounds__(128, 4) void attn_kernel()
{
    extern __shared__ __half smh[];
    __half* Qs = smh;                       // [128][KVP]
    __half* KVs = smh + Q_SZ;               // [buf][K|V][64*KVP]

    const int tid = threadIdx.x;
    const int w = tid >> 5, lane = tid & 31, g = lane >> 2, c = lane & 3;
    const int q0 = blockIdx.x * 128;
    const int bh = blockIdx.y;
    const int b_ = bh >> 4, h = bh & 15, kv = h >> 2;

    const __half* qg = &g_q[((size_t)(b_ * 16 + h)) * NTOK * 64];
    const __half* kg = &g_k[((size_t)(b_ * 4 + kv)) * NTOK * 64];
    const __half* vg = &g_vt[((size_t)(b_ * 4 + kv)) * 64 * NTOK];

    const uint32_t qs_u = smem_u32(Qs);
    const int lr = tid >> 1, lc = tid & 1;
    const uint32_t k_u = smem_u32(KVs) + lr * (KVP * 2) + lc * 64;
    const uint32_t v_u = k_u + KV_T * 2;
    const uint32_t bufstride = 2 * KV_T * 2;   // bytes

    const int m_ = lane >> 3, r_ = lane & 7;
    const uint32_t a_off = ((m_ & 1) * 8 + r_) * (KVP * 2) + (m_ >> 1) * 16;
    const uint32_t b_off = ((m_ >> 1) * 8 + r_) * (KVP * 2) + (m_ & 1) * 16;
    const uint32_t qbase = qs_u + (w * 32) * (KVP * 2) + a_off;
    const uint32_t kbase = smem_u32(KVs) + b_off;
    const uint32_t vbase = kbase + KV_T * 2;

    // prologue: Q (row tid) + K0 + V0
    {
        const uint32_t qdst = qs_u + tid * (KVP * 2);
        const __half* qsrc = &qg[(size_t)(q0 + tid) * 64];
        #pragma unroll
        for (int i = 0; i < 8; i++)
            CP_ASYNC16(qdst + i * 16, qsrc + i * 8);
    }
    #pragma unroll
    for (int i = 0; i < 4; i++) {
        CP_ASYNC16(k_u + i * 16, &kg[(size_t)lr * 64 + lc * 32 + i * 8]);
        CP_ASYNC16(v_u + i * 16, &vg[(size_t)lr * NTOK + lc * 32 + i * 8]);
    }
    CP_COMMIT();

    float o[2][8][4] = {};
    float lpa[2][4] = {};

    for (int kt = 0; kt < NTOK; kt += 64) {
        const int buf = (kt >> 6) & 1;
        CP_WAIT0();
        __syncthreads();

        if (kt + 64 < NTOK) {
            const uint32_t off = (1 - buf) * bufstride;
            #pragma unroll
            for (int i = 0; i < 4; i++) {
                CP_ASYNC16(k_u + off + i * 16, &kg[(size_t)(kt + 64 + lr) * 64 + lc * 32 + i * 8]);
                CP_ASYNC16(v_u + off + i * 16, &vg[(size_t)lr * NTOK + kt + 64 + lc * 32 + i * 8]);
            }
            CP_COMMIT();
        }

        const uint32_t kb = kbase + buf * bufstride;
        const uint32_t vb = vbase + buf * bufstride;

        // per 16-key chunk: S-partial -> ex2 -> PV  (keeps regs low)
        #pragma unroll
        for (int p = 0; p < 4; p++) {
            float s[2][2][4] = {};
            #pragma unroll
            for (int kc = 0; kc < 4; kc++) {
                uint32_t b0a, b1a, b0b, b1b;
                LDSM4(b0a, b1a, b0b, b1b, kb + p * 16 * (KVP * 2) + kc * 32);
                #pragma unroll
                for (int mt = 0; mt < 2; mt++) {
                    uint32_t qa0, qa1, qa2, qa3;
                    LDSM4(qa0, qa1, qa2, qa3, qbase + mt * 16 * (KVP * 2) + kc * 32);
                    mma16(s[mt][0], qa0, qa1, qa2, qa3, b0a, b1a);
                    mma16(s[mt][1], qa0, qa1, qa2, qa3, b0b, b1b);
                }
            }

            uint32_t pa[2][4];
            #pragma unroll
            for (int mt = 0; mt < 2; mt++) {
                pa[mt][0] = EX2H2(PK2(s[mt][0][0], s[mt][0][1]));
                pa[mt][1] = EX2H2(PK2(s[mt][0][2], s[mt][0][3]));
                pa[mt][2] = EX2H2(PK2(s[mt][1][0], s[mt][1][1]));
                pa[mt][3] = EX2H2(PK2(s[mt][1][2], s[mt][1][3]));
                mma16(lpa[mt], pa[mt][0], pa[mt][1], pa[mt][2], pa[mt][3],
                      H2_ONES, H2_ONES);
            }

            #pragma unroll
            for (int p2 = 0; p2 < 4; p2++) {
                uint32_t b0a, b1a, b0b, b1b;
                LDSM4(b0a, b1a, b0b, b1b, vb + p2 * 16 * (KVP * 2) + p * 32);
                #pragma unroll
                for (int mt = 0; mt < 2; mt++) {
                    mma16(o[mt][2 * p2],     pa[mt][0], pa[mt][1], pa[mt][2], pa[mt][3], b0a, b1a);
                    mma16(o[mt][2 * p2 + 1], pa[mt][0], pa[mt][1], pa[mt][2], pa[mt][3], b0b, b1b);
                }
            }
        }
    }

    #pragma unroll
    for (int mt = 0; mt < 2; mt++) {
        float inv0 = 1.f / lpa[mt][0], inv1 = 1.f / lpa[mt][2];
        int n0 = q0 + w * 32 + mt * 16 + g, n1 = n0 + 8;
        __half* ob0 = &g_o[((size_t)(b_ * NTOK + n0)) * 1024 + h * 64];
        __half* ob1 = &g_o[((size_t)(b_ * NTOK + n1)) * 1024 + h * 64];
        #pragma unroll
        for (int nt = 0; nt < 8; nt++) {
            int d0 = nt * 8 + 2 * c;
            *(uint32_t*)&ob0[d0] = PK2(o[mt][nt][0] * inv0, o[mt][nt][1] * inv0);
            *(uint32_t*)&ob1[d0] = PK2(o[mt][nt][2] * inv1, o[mt][nt][3] * inv1);
        }
    }
}

// =============================================================================
// Kernel 3: out = O @ Wo + bo  (fp16 operands, fp32 out)
// =============================================================================
__global__ __launch_bounds__(128) void out_kernel(
    const float* __restrict__ bo, float* __restrict__ out)
{
    __shared__ __half sa[2 * A_SZ];
    __shared__ __half sb[2 * B_SZ];
    const int tid = threadIdx.x;
    const int w = tid >> 5, lane = tid & 31, g = lane >> 2, c = lane & 3;
    const int m0 = blockIdx.y * 128;
    const int colb = blockIdx.x * 64;

    float acc[2][8][4] = {};
    gemm_fp16(g_o + (size_t)m0 * 1024, g_wot + (size_t)colb * 1024,
              sa, sb, tid, w, lane, acc);

    #pragma unroll
    for (int mt = 0; mt < 2; mt++) {
        int m_a = m0 + w * 32 + mt * 16 + g;
        float* r0 = &out[(size_t)m_a * 1024 + colb];
        float* r1 = &out[(size_t)(m_a + 8) * 1024 + colb];
        #pragma unroll
        for (int nt = 0; nt < 8; nt++) {
            int d0 = nt * 8 + 2 * c;
            float b0v = bo[colb + d0], b1v = bo[colb + d0 + 1];
            *(float2*)&r0[d0] = make_float2(acc[mt][nt][0] + b0v, acc[mt][nt][1] + b1v);
            *(float2*)&r1[d0] = make_float2(acc[mt][nt][2] + b0v, acc[mt][nt][3] + b1v);
        }
    }
}

// =============================================================================
extern "C" void kernel_launch(void* const* d_in, const int* in_sizes, int n_in,
                              void* d_out, int out_size)
{
    const float* x  = (const float*)d_in[0];
    const float* Wq = (const float*)d_in[1];
    const float* bq = (const float*)d_in[2];
    const float* Wk = (const float*)d_in[3];
    const float* bk = (const float*)d_in[4];
    const float* Wv = (const float*)d_in[5];
    const float* bv = (const float*)d_in[6];
    const float* Wo = (const float*)d_in[7];
    const float* bo = (const float*)d_in[8];
    const float* qn = (const float*)d_in[9];
    const float* kn = (const float*)d_in[10];
    float* out = (float*)d_out;

    cudaFuncSetAttribute(attn_kernel, cudaFuncAttributeMaxDynamicSharedMemorySize, ATTN_SMEM);

    cvtx_kernel<<<4096, 256>>>((const float4*)x);
    wtr_kernel<<<2560, 256>>>(Wq, Wk, Wv, Wo);
    qkv_kernel<<<dim3(24, 32), 128>>>(bq, bk, bv, qn, kn);
    attn_kernel<<<dim3(16, 32), 128, ATTN_SMEM>>>();
    out_kernel<<<dim3(16, 32), 128>>>(bo, out);
}

// round 15
// speedup vs baseline: 1.1812x; 1.1499x over previous
#include <cuda_runtime.h>
#include <cuda_fp16.h>
#include <math.h>
#include <stdint.h>

#define NTOK 2048

// ---------------- scratch (fp16 operands) ----------------
__device__ __half g_xh [(size_t)4096 * 1024];       // x       [m][k]
__device__ __half g_wqt[(size_t)1024 * 1024];       // Wq^T    [n][k]
__device__ __half g_wkt[(size_t)256  * 1024];
__device__ __half g_wvt[(size_t)256  * 1024];
__device__ __half g_wot[(size_t)1024 * 1024];
__device__ __half g_q [(size_t)2 * 16 * NTOK * 64]; // [b][h][n][d], q*(log2e/8)
__device__ __half g_k [(size_t)2 * 4  * NTOK * 64];
__device__ __half g_vt[(size_t)2 * 4  * 64 * NTOK]; // [b][kv][d][n]
__device__ __half g_o [(size_t)4096 * 1024];

__device__ __forceinline__ uint32_t PK2(float a, float b) {
    __half2 h = __floats2half2_rn(a, b);
    return *(uint32_t*)&h;
}
__device__ __forceinline__ uint32_t EX2H2(uint32_t x) {
    uint32_t y; asm("ex2.approx.f16x2 %0, %1;" : "=r"(y) : "r"(x));
    return y;
}
__device__ __forceinline__ uint32_t smem_u32(const void* p) {
    uint32_t a;
    asm("{ .reg .u64 t; cvta.to.shared.u64 t, %1; cvt.u32.u64 %0, t; }"
        : "=r"(a) : "l"(p));
    return a;
}

// D(16x8,f32) += A(16x16,f16) * B(16x8,f16)
__device__ __forceinline__ void mma16(float* d, uint32_t a0, uint32_t a1,
                                      uint32_t a2, uint32_t a3,
                                      uint32_t b0, uint32_t b1) {
    asm volatile(
        "mma.sync.aligned.m16n8k16.row.col.f32.f16.f16.f32 "
        "{%0,%1,%2,%3},{%4,%5,%6,%7},{%8,%9},{%0,%1,%2,%3};\n"
        : "+f"(d[0]), "+f"(d[1]), "+f"(d[2]), "+f"(d[3])
        : "r"(a0), "r"(a1), "r"(a2), "r"(a3), "r"(b0), "r"(b1));
}

// D(16x8,f16x2 packed) += A(16x16,f16) * B(16x8,f16)   -- fp16 accumulate
__device__ __forceinline__ void mmah(uint32_t* d, uint32_t a0, uint32_t a1,
                                     uint32_t a2, uint32_t a3,
                                     uint32_t b0, uint32_t b1) {
    asm volatile(
        "mma.sync.aligned.m16n8k16.row.col.f16.f16.f16.f16 "
        "{%0,%1},{%2,%3,%4,%5},{%6,%7},{%0,%1};\n"
        : "+r"(d[0]), "+r"(d[1])
        : "r"(a0), "r"(a1), "r"(a2), "r"(a3), "r"(b0), "r"(b1));
}

#define LDSM4(r0, r1, r2, r3, addr) \
    asm volatile("ldmatrix.sync.aligned.m8n8.x4.shared.b16 {%0,%1,%2,%3}, [%4];" \
                 : "=r"(r0), "=r"(r1), "=r"(r2), "=r"(r3) : "r"(addr))

#define CP_ASYNC16(dst, src) \
    asm volatile("cp.async.cg.shared.global [%0], [%1], 16;\n" :: "r"(dst), "l"(src))
#define CP_COMMIT() asm volatile("cp.async.commit_group;\n" ::: "memory")
#define CP_WAIT0()  asm volatile("cp.async.wait_group 0;\n" ::: "memory")
#define CP_WAIT1()  asm volatile("cp.async.wait_group 1;\n" ::: "memory")

// =============================================================================
// Prep A: x -> fp16
// =============================================================================
__global__ __launch_bounds__(256) void cvtx_kernel(const float4* __restrict__ x)
{
    int i = blockIdx.x * 256 + threadIdx.x;   // 1048576 float4
    float4 v = x[i];
    uint2 o;
    o.x = PK2(v.x, v.y);
    o.y = PK2(v.z, v.w);
    ((uint2*)g_xh)[i] = o;
}

// =============================================================================
// Prep B: weights -> fp16 + transpose to [n][k]
// =============================================================================
__global__ __launch_bounds__(256) void wtr_kernel(
    const float* __restrict__ wq, const float* __restrict__ wk,
    const float* __restrict__ wv, const float* __restrict__ wo)
{
    __shared__ float ts[32][33];
    int t = blockIdx.x;
    const float* src; __half* dst; int N;
    if (t < 1024)      { src = wq; dst = g_wqt; N = 1024; }
    else if (t < 1280) { src = wk; dst = g_wkt; N = 256;  t -= 1024; }
    else if (t < 1536) { src = wv; dst = g_wvt; N = 256;  t -= 1280; }
    else               { src = wo; dst = g_wot; N = 1024; t -= 1536; }
    int tiles_n = N >> 5;
    int k0 = (t / tiles_n) << 5, n0 = (t % tiles_n) << 5;
    int tx = threadIdx.x & 31, ty = threadIdx.x >> 5;
    #pragma unroll
    for (int p = 0; p < 4; p++)
        ts[ty + p * 8][tx] = src[(size_t)(k0 + ty + p * 8) * N + n0 + tx];
    __syncthreads();
    #pragma unroll
    for (int p = 0; p < 4; p++)
        dst[(size_t)(n0 + ty + p * 8) * 1024 + k0 + tx] = __float2half(ts[tx][ty + p * 8]);
}

// =============================================================================
// fp16 GEMM mainloop: 128 thr / 4 warps, tile 128x64, k-step 32, 2-stage.
// =============================================================================
#define APAD 40
#define A_SZ (128 * APAD)
#define B_SZ (64 * APAD)

__device__ __forceinline__ void gemm_fp16(
    const __half* __restrict__ A, const __half* __restrict__ Bt,
    __half* sa, __half* sb, int tid, int w, int lane, float acc[2][8][4])
{
    const uint32_t as_u = smem_u32(sa);
    const uint32_t bs_u = smem_u32(sb);
    const int ldr = tid >> 2, ldc = tid & 3;

    const int m_ = lane >> 3, r_ = lane & 7;
    const uint32_t a_off = ((m_ & 1) * 8 + r_) * (APAD * 2) + (m_ >> 1) * 16;
    const uint32_t b_off = ((m_ >> 1) * 8 + r_) * (APAD * 2) + (m_ & 1) * 16;

    #pragma unroll
    for (int p = 0; p < 4; p++)
        CP_ASYNC16(as_u + ((p * 32 + ldr) * APAD) * 2 + ldc * 16,
                   &A[(size_t)(p * 32 + ldr) * 1024 + ldc * 8]);
    #pragma unroll
    for (int p = 0; p < 2; p++)
        CP_ASYNC16(bs_u + ((p * 32 + ldr) * APAD) * 2 + ldc * 16,
                   &Bt[(size_t)(p * 32 + ldr) * 1024 + ldc * 8]);
    CP_COMMIT();

    for (int i = 0; i < 32; i++) {
        const int cur = i & 1;
        if (i + 1 < 32) {
            const int nxt = 1 - cur;
            const int k0 = (i + 1) * 32;
            #pragma unroll
            for (int p = 0; p < 4; p++)
                CP_ASYNC16(as_u + (nxt * A_SZ + (p * 32 + ldr) * APAD) * 2 + ldc * 16,
                           &A[(size_t)(p * 32 + ldr) * 1024 + k0 + ldc * 8]);
            #pragma unroll
            for (int p = 0; p < 2; p++)
                CP_ASYNC16(bs_u + (nxt * B_SZ + (p * 32 + ldr) * APAD) * 2 + ldc * 16,
                           &Bt[(size_t)(p * 32 + ldr) * 1024 + k0 + ldc * 8]);
            CP_COMMIT();
            CP_WAIT1();
        } else {
            CP_WAIT0();
        }
        __syncthreads();

        const uint32_t ab = as_u + cur * A_SZ * 2;
        const uint32_t bb = bs_u + cur * B_SZ * 2;
        #pragma unroll
        for (int ks = 0; ks < 2; ks++) {
            uint32_t af[2][4];
            #pragma unroll
            for (int mt = 0; mt < 2; mt++)
                LDSM4(af[mt][0], af[mt][1], af[mt][2], af[mt][3],
                      ab + (w * 32 + mt * 16) * (APAD * 2) + ks * 32 + a_off);
            #pragma unroll
            for (int p = 0; p < 4; p++) {
                uint32_t b0a, b1a, b0b, b1b;
                LDSM4(b0a, b1a, b0b, b1b,
                      bb + (p * 16) * (APAD * 2) + ks * 32 + b_off);
                #pragma unroll
                for (int mt = 0; mt < 2; mt++) {
                    mma16(acc[mt][2 * p],     af[mt][0], af[mt][1], af[mt][2], af[mt][3], b0a, b1a);
                    mma16(acc[mt][2 * p + 1], af[mt][0], af[mt][1], af[mt][2], af[mt][3], b0b, b1b);
                }
            }
        }
        __syncthreads();
    }
}

// =============================================================================
// Kernel 1: QKV GEMM + bias + RMSNorm + 3D RoPE + q-scale (0.125*log2e)
// =============================================================================
__global__ __launch_bounds__(128) void qkv_kernel(
    const float* __restrict__ bq, const float* __restrict__ bk,
    const float* __restrict__ bv,
    const float* __restrict__ qn, const float* __restrict__ kn)
{
    __shared__ __half sa[2 * A_SZ];
    __shared__ __half sb[2 * B_SZ];
    const int tid = threadIdx.x;
    const int w = tid >> 5, lane = tid & 31, g = lane >> 2, c = lane & 3;
    const int m0 = blockIdx.y * 128;
    const int colb = blockIdx.x * 64;

    const __half* Bt; const float* bias; int seg, colloc;
    if (colb < 1024)      { Bt = g_wqt; bias = bq; seg = 0; colloc = colb; }
    else if (colb < 1280) { Bt = g_wkt; bias = bk; seg = 1; colloc = colb - 1024; }
    else                  { Bt = g_wvt; bias = bv; seg = 2; colloc = colb - 1280; }

    float acc[2][8][4] = {};
    gemm_fp16(g_xh + (size_t)m0 * 1024, Bt + (size_t)colloc * 1024,
              sa, sb, tid, w, lane, acc);

    #pragma unroll
    for (int nt = 0; nt < 8; nt++) {
        float b0v = bias[colloc + nt * 8 + 2 * c];
        float b1v = bias[colloc + nt * 8 + 2 * c + 1];
        #pragma unroll
        for (int mt = 0; mt < 2; mt++) {
            acc[mt][nt][0] += b0v; acc[mt][nt][1] += b1v;
            acc[mt][nt][2] += b0v; acc[mt][nt][3] += b1v;
        }
    }

    const int head = colloc >> 6;

    if (seg == 2) {
        #pragma unroll
        for (int mt = 0; mt < 2; mt++) {
            int m_a = m0 + w * 32 + mt * 16 + g;
            int b_ = m_a >> 11, n0 = m_a & 2047, n1 = n0 + 8;
            __half* vb = &g_vt[((size_t)(b_ * 4 + head)) * 64 * NTOK];
            #pragma unroll
            for (int nt = 0; nt < 8; nt++) {
                int d0 = nt * 8 + 2 * c;
                vb[(size_t)d0 * NTOK + n0]       = __float2half(acc[mt][nt][0]);
                vb[(size_t)(d0 + 1) * NTOK + n0] = __float2half(acc[mt][nt][1]);
                vb[(size_t)d0 * NTOK + n1]       = __float2half(acc[mt][nt][2]);
                vb[(size_t)(d0 + 1) * NTOK + n1] = __float2half(acc[mt][nt][3]);
            }
        }
        return;
    }

    // RMSNorm (intra-warp over 64-wide head dim)
    const float* nw = (seg == 0) ? qn : kn;
    #pragma unroll
    for (int mt = 0; mt < 2; mt++) {
        float ss0 = 0.f, ss1 = 0.f;
        #pragma unroll
        for (int nt = 0; nt < 8; nt++) {
            ss0 += acc[mt][nt][0] * acc[mt][nt][0] + acc[mt][nt][1] * acc[mt][nt][1];
            ss1 += acc[mt][nt][2] * acc[mt][nt][2] + acc[mt][nt][3] * acc[mt][nt][3];
        }
        ss0 += __shfl_xor_sync(~0u, ss0, 1); ss0 += __shfl_xor_sync(~0u, ss0, 2);
        ss1 += __shfl_xor_sync(~0u, ss1, 1); ss1 += __shfl_xor_sync(~0u, ss1, 2);
        float rs0 = rsqrtf(ss0 * (1.f / 64.f) + 1e-6f);
        float rs1 = rsqrtf(ss1 * (1.f / 64.f) + 1e-6f);
        #pragma unroll
        for (int nt = 0; nt < 8; nt++) {
            float w0 = nw[nt * 8 + 2 * c], w1 = nw[nt * 8 + 2 * c + 1];
            acc[mt][nt][0] *= rs0 * w0; acc[mt][nt][1] *= rs0 * w1;
            acc[mt][nt][2] *= rs1 * w0; acc[mt][nt][3] *= rs1 * w1;
        }
    }

    // 3D RoPE in-place: pairs t:(0,1) h:(2,3) w:(4,6),(5,7)
    const int lo_[4] = {0, 2, 4, 5};
    const int hi_[4] = {1, 3, 6, 7};
    #pragma unroll
    for (int mt = 0; mt < 2; mt++) {
        int m_a = m0 + w * 32 + mt * 16 + g;
        int n0 = m_a & 2047, n1 = n0 + 8;
        float posr[2][3] = {
            {(float)(n0 >> 8), (float)((n0 >> 4) & 15), (float)(n0 & 15)},
            {(float)(n1 >> 8), (float)((n1 >> 4) & 15), (float)(n1 & 15)}};
        #pragma unroll
        for (int pi = 0; pi < 4; pi++) {
            int lo = lo_[pi], hi = hi_[pi];
            int ax = (pi == 0) ? 0 : (pi == 1 ? 1 : 2);
            float halfinv = (pi < 2) ? (1.f / 8.f) : (1.f / 16.f);
            #pragma unroll
            for (int e = 0; e < 2; e++) {
                float f = (pi < 2) ? (float)(2 * c + e)
                                   : (float)((lo & 1) * 8 + 2 * c + e);
                float inv = __powf(10000.f, -f * halfinv);
                #pragma unroll
                for (int r = 0; r < 2; r++) {
                    float sv, cv;
                    __sincosf(posr[r][ax] * inv, &sv, &cv);
                    float xl = acc[mt][lo][2 * r + e];
                    float xh = acc[mt][hi][2 * r + e];
                    acc[mt][lo][2 * r + e] = xl * cv - xh * sv;
                    acc[mt][hi][2 * r + e] = xh * cv + xl * sv;
                }
            }
        }
    }

    float sc = (seg == 0) ? (0.125f * 1.4426950408889634f) : 1.f;
    #pragma unroll
    for (int mt = 0; mt < 2; mt++) {
        int m_a = m0 + w * 32 + mt * 16 + g;
        int b_ = m_a >> 11, n0 = m_a & 2047, n1 = n0 + 8;
        __half* qb = (seg == 0) ? &g_q[((size_t)(b_ * 16 + head)) * NTOK * 64]
                                : &g_k[((size_t)(b_ * 4 + head)) * NTOK * 64];
        #pragma unroll
        for (int nt = 0; nt < 8; nt++) {
            int d0 = nt * 8 + 2 * c;
            *(uint32_t*)&qb[(size_t)n0 * 64 + d0] = PK2(acc[mt][nt][0] * sc, acc[mt][nt][1] * sc);
            *(uint32_t*)&qb[(size_t)n1 * 64 + d0] = PK2(acc[mt][nt][2] * sc, acc[mt][nt][3] * sc);
        }
    }
}

// =============================================================================
// Kernel 2: flash attention. q-block 256, 8 warps, warp M=32.
//   Grid 256 CTAs -> ONE WAVE at 2 CTAs/SM (256 thr, <=125 regs).
//   S accumulated in fp16 (packed; D-frag == PV A-frag; no PK2); ex2 in place.
//   Q in smem (loaded once per CTA); K+V double-buffered; rowsum via ones-mma.
// =============================================================================
#define KVP 72
#define Q_SZh (256 * KVP)               // 18432 halfs
#define KV_SZh (64 * KVP)               // 4608 halfs per K or V tile
#define ATTN_SMEM ((Q_SZh + 4 * KV_SZh) * 2)   // 73728 bytes
#define H2_ONES 0x3C003C00u

__global__ __launch_bounds__(256, 2) void attn_kernel()
{
    extern __shared__ __half smh[];
    __half* Qs  = smh;                  // [256][KVP]
    __half* KVs = smh + Q_SZh;          // [buf][K|V]

    const int tid = threadIdx.x;
    const int w = tid >> 5, lane = tid & 31, g = lane >> 2, c = lane & 3;
    const int q0 = blockIdx.x * 256;
    const int bh = blockIdx.y;
    const int b_ = bh >> 4, h = bh & 15, kv = h >> 2;

    const __half* qg = &g_q[((size_t)(b_ * 16 + h)) * NTOK * 64];
    const __half* kg = &g_k[((size_t)(b_ * 4 + kv)) * NTOK * 64];
    const __half* vg = &g_vt[((size_t)(b_ * 4 + kv)) * 64 * NTOK];

    const uint32_t qs_u = smem_u32(Qs);
    const int lr = tid >> 2, lq = (tid & 3) * 16;   // K/V loader: 64 rows x 4 thr
    const uint32_t k_u = smem_u32(KVs) + lr * (KVP * 2) + (tid & 3) * 32;
    const uint32_t v_u = k_u + KV_SZh * 2;
    const uint32_t bufstride = 2 * KV_SZh * 2;      // bytes

    const int m_ = lane >> 3, r_ = lane & 7;
    const uint32_t a_off = ((m_ & 1) * 8 + r_) * (KVP * 2) + (m_ >> 1) * 16;
    const uint32_t b_off = ((m_ >> 1) * 8 + r_) * (KVP * 2) + (m_ & 1) * 16;
    const uint32_t qbase = qs_u + (w * 32) * (KVP * 2) + a_off;
    const uint32_t kbase = smem_u32(KVs) + b_off;
    const uint32_t vbase = kbase + KV_SZh * 2;

    // prologue: Q (row tid of 256) + K0 + V0
    {
        const uint32_t qdst = qs_u + tid * (KVP * 2);
        const __half* qsrc = &qg[(size_t)(q0 + tid) * 64];
        #pragma unroll
        for (int i = 0; i < 8; i++)
            CP_ASYNC16(qdst + i * 16, qsrc + i * 8);
    }
    CP_ASYNC16(k_u,      &kg[(size_t)lr * 64 + lq]);
    CP_ASYNC16(k_u + 16, &kg[(size_t)lr * 64 + lq + 8]);
    CP_ASYNC16(v_u,      &vg[(size_t)lr * NTOK + lq]);
    CP_ASYNC16(v_u + 16, &vg[(size_t)lr * NTOK + lq + 8]);
    CP_COMMIT();

    float o[2][8][4] = {};
    float lpa[2][4] = {};

    for (int kt = 0; kt < NTOK; kt += 64) {
        const int buf = (kt >> 6) & 1;
        CP_WAIT0();
        __syncthreads();    // K(t),V(t) resident; all warps done with t-1

        if (kt + 64 < NTOK) {
            const uint32_t off = (1 - buf) * bufstride;
            CP_ASYNC16(k_u + off,      &kg[(size_t)(kt + 64 + lr) * 64 + lq]);
            CP_ASYNC16(k_u + off + 16, &kg[(size_t)(kt + 64 + lr) * 64 + lq + 8]);
            CP_ASYNC16(v_u + off,      &vg[(size_t)lr * NTOK + kt + 64 + lq]);
            CP_ASYNC16(v_u + off + 16, &vg[(size_t)lr * NTOK + kt + 64 + lq + 8]);
            CP_COMMIT();
        }

        const uint32_t kb = kbase + buf * bufstride;
        const uint32_t vb = vbase + buf * bufstride;

        // S = Q K^T, fp16 accumulate (kc outer -> Q frags loaded once per kc)
        uint32_t s[4][2][4] = {};    // [key-chunk p][mt][4 packed regs]
        #pragma unroll
        for (int kc = 0; kc < 4; kc++) {
            uint32_t qa[2][4];
            LDSM4(qa[0][0], qa[0][1], qa[0][2], qa[0][3], qbase + kc * 32);
            LDSM4(qa[1][0], qa[1][1], qa[1][2], qa[1][3],
                  qbase + 16 * (KVP * 2) + kc * 32);
            #pragma unroll
            for (int p = 0; p < 4; p++) {
                uint32_t b0a, b1a, b0b, b1b;
                LDSM4(b0a, b1a, b0b, b1b, kb + p * 16 * (KVP * 2) + kc * 32);
                #pragma unroll
                for (int mt = 0; mt < 2; mt++) {
                    mmah(&s[p][mt][0], qa[mt][0], qa[mt][1], qa[mt][2], qa[mt][3], b0a, b1a);
                    mmah(&s[p][mt][2], qa[mt][0], qa[mt][1], qa[mt][2], qa[mt][3], b0b, b1b);
                }
            }
        }

        // P = 2^S in place (packed fp16); rowsum via ones-mma (f32 accum)
        #pragma unroll
        for (int p = 0; p < 4; p++)
            #pragma unroll
            for (int mt = 0; mt < 2; mt++) {
                s[p][mt][0] = EX2H2(s[p][mt][0]);
                s[p][mt][1] = EX2H2(s[p][mt][1]);
                s[p][mt][2] = EX2H2(s[p][mt][2]);
                s[p][mt][3] = EX2H2(s[p][mt][3]);
                mma16(lpa[mt], s[p][mt][0], s[p][mt][1], s[p][mt][2], s[p][mt][3],
                      H2_ONES, H2_ONES);
            }

        // O += P V  (S D-frags ARE the A-frags; f32 accumulate)
        #pragma unroll
        for (int p = 0; p < 4; p++) {
            #pragma unroll
            for (int p2 = 0; p2 < 4; p2++) {
                uint32_t v0, v1, v2, v3;
                LDSM4(v0, v1, v2, v3, vb + p2 * 16 * (KVP * 2) + p * 32);
                #pragma unroll
                for (int mt = 0; mt < 2; mt++) {
                    mma16(o[mt][2 * p2],     s[p][mt][0], s[p][mt][1], s[p][mt][2], s[p][mt][3], v0, v1);
                    mma16(o[mt][2 * p2 + 1], s[p][mt][0], s[p][mt][1], s[p][mt][2], s[p][mt][3], v2, v3);
                }
            }
        }
    }

    #pragma unroll
    for (int mt = 0; mt < 2; mt++) {
        float inv0 = 1.f / lpa[mt][0], inv1 = 1.f / lpa[mt][2];
        int n0 = q0 + w * 32 + mt * 16 + g, n1 = n0 + 8;
        __half* ob0 = &g_o[((size_t)(b_ * NTOK + n0)) * 1024 + h * 64];
        __half* ob1 = &g_o[((size_t)(b_ * NTOK + n1)) * 1024 + h * 64];
        #pragma unroll
        for (int nt = 0; nt < 8; nt++) {
            int d0 = nt * 8 + 2 * c;
            *(uint32_t*)&ob0[d0] = PK2(o[mt][nt][0] * inv0, o[mt][nt][1] * inv0);
            *(uint32_t*)&ob1[d0] = PK2(o[mt][nt][2] * inv1, o[mt][nt][3] * inv1);
        }
    }
}

// =============================================================================
// Kernel 3: out = O @ Wo + bo  (fp16 operands, fp32 out)
// =============================================================================
__global__ __launch_bounds__(128) void out_kernel(
    const float* __restrict__ bo, float* __restrict__ out)
{
    __shared__ __half sa[2 * A_SZ];
    __shared__ __half sb[2 * B_SZ];
    const int tid = threadIdx.x;
    const int w = tid >> 5, lane = tid & 31, g = lane >> 2, c = lane & 3;
    const int m0 = blockIdx.y * 128;
    const int colb = blockIdx.x * 64;

    float acc[2][8][4] = {};
    gemm_fp16(g_o + (size_t)m0 * 1024, g_wot + (size_t)colb * 1024,
              sa, sb, tid, w, lane, acc);

    #pragma unroll
    for (int mt = 0; mt < 2; mt++) {
        int m_a = m0 + w * 32 + mt * 16 + g;
        float* r0 = &out[(size_t)m_a * 1024 + colb];
        float* r1 = &out[(size_t)(m_a + 8) * 1024 + colb];
        #pragma unroll
        for (int nt = 0; nt < 8; nt++) {
            int d0 = nt * 8 + 2 * c;
            float b0v = bo[colb + d0], b1v = bo[colb + d0 + 1];
            *(float2*)&r0[d0] = make_float2(acc[mt][nt][0] + b0v, acc[mt][nt][1] + b1v);
            *(float2*)&r1[d0] = make_float2(acc[mt][nt][2] + b0v, acc[mt][nt][3] + b1v);
        }
    }
}

// =============================================================================
extern "C" void kernel_launch(void* const* d_in, const int* in_sizes, int n_in,
                              void* d_out, int out_size)
{
    const float* x  = (const float*)d_in[0];
    const float* Wq = (const float*)d_in[1];
    const float* bq = (const float*)d_in[2];
    const float* Wk = (const float*)d_in[3];
    const float* bk = (const float*)d_in[4];
    const float* Wv = (const float*)d_in[5];
    const float* bv = (const float*)d_in[6];
    const float* Wo = (const float*)d_in[7];
    const float* bo = (const float*)d_in[8];
    const float* qn = (const float*)d_in[9];
    const float* kn = (const float*)d_in[10];
    float* out = (float*)d_out;

    cudaFuncSetAttribute(attn_kernel, cudaFuncAttributeMaxDynamicSharedMemorySize, ATTN_SMEM);

    cvtx_kernel<<<4096, 256>>>((const float4*)x);
    wtr_kernel<<<2560, 256>>>(Wq, Wk, Wv, Wo);
    qkv_kernel<<<dim3(24, 32), 128>>>(bq, bk, bv, qn, kn);
    attn_kernel<<<dim3(8, 32), 256, ATTN_SMEM>>>();
    out_kernel<<<dim3(16, 32), 128>>>(bo, out);
}